// round 2
// baseline (speedup 1.0000x reference)
#include <cuda_runtime.h>
#include <math.h>

#define Bsz 8192
#define Knod 16
#define Eedg 64
#define FIN 300
#define FOUT 64
#define ALPHA 1.0f
#define BETA 0.6f

// Scratch (static device globals; no runtime allocation)
static __device__ float g_Y[3u * Bsz * Knod * FOUT];   // encoder GEMM output, 100 MB
static __device__ float g_ssq1[Bsz];
static __device__ float g_ssq2[Bsz];
static __device__ float g_lt1[Bsz];
static __device__ float g_lt2[Bsz];
static __device__ float g_contr[Bsz];
static __device__ float g_gen;

// ---------------------------------------------------------------------------
// Kernel 1: Y = feat @ W_enc  (per tensor z=0,1,2).  M=131072, K=300, N=64
// 64x64 tile, BK=32, 256 threads, 4x4 per thread, fp32 FFMA.
// ---------------------------------------------------------------------------
__global__ void __launch_bounds__(256) gemm_enc(
    const float* __restrict__ f1, const float* __restrict__ f2,
    const float* __restrict__ fn, const float* __restrict__ W)
{
    const int z = blockIdx.z;
    const float* A = (z == 0) ? f1 : (z == 1) ? f2 : fn;
    const int m0 = blockIdx.x * 64;
    const int tid = threadIdx.x;
    const int tx = tid & 15, ty = tid >> 4;

    __shared__ float As[32][68];
    __shared__ float Bs[32][68];

    float acc[4][4];
#pragma unroll
    for (int i = 0; i < 4; i++)
#pragma unroll
        for (int q = 0; q < 4; q++) acc[i][q] = 0.f;

    const int kA = tid & 31, mA = tid >> 5;   // A: 8 rows/thread-iter, 32 k per row-chunk
    const int nB = tid & 63, kB = tid >> 6;   // B: 4 k-rows per iter

    for (int it = 0; it < 10; it++) {
        const int k0 = it * 32;
        // load A tile transposed: As[k][m]
#pragma unroll
        for (int j = 0; j < 8; j++) {
            int m = mA + 8 * j;
            int kg = k0 + kA;
            float v = (kg < FIN) ? A[(long)(m0 + m) * FIN + kg] : 0.f;
            As[kA][m] = v;
        }
        // load B tile: Bs[k][n]
#pragma unroll
        for (int j = 0; j < 8; j++) {
            int kk = kB + 4 * j;
            int kg = k0 + kk;
            Bs[kk][nB] = (kg < FIN) ? W[kg * FOUT + nB] : 0.f;
        }
        __syncthreads();

#pragma unroll
        for (int kk = 0; kk < 32; kk++) {
            float4 a4 = *(const float4*)&As[kk][ty * 4];
            float4 b4 = *(const float4*)&Bs[kk][tx * 4];
            float a[4] = {a4.x, a4.y, a4.z, a4.w};
            float b[4] = {b4.x, b4.y, b4.z, b4.w};
#pragma unroll
            for (int i = 0; i < 4; i++)
#pragma unroll
                for (int q = 0; q < 4; q++) acc[i][q] += a[i] * b[q];
        }
        __syncthreads();
    }

    float* Yout = g_Y + ((long)z * (Bsz * Knod) + m0) * FOUT;
#pragma unroll
    for (int i = 0; i < 4; i++) {
        float4 v = make_float4(acc[i][0], acc[i][1], acc[i][2], acc[i][3]);
        *(float4*)&Yout[(ty * 4 + i) * FOUT + tx * 4] = v;
    }
}

// ---------------------------------------------------------------------------
// Kernel 2: per-graph pipeline. One 128-thread CTA per graph.
// ---------------------------------------------------------------------------
__device__ __forceinline__ float blockReduceSum(float v, volatile float* sRed) {
    int tid = threadIdx.x;
    sRed[tid] = v;
    __syncthreads();
    for (int s = 64; s > 0; s >>= 1) {
        if (tid < s) sRed[tid] += sRed[tid + s];
        __syncthreads();
    }
    float r = sRed[0];
    __syncthreads();
    return r;
}

__global__ void __launch_bounds__(128) graph_kernel(
    const float* __restrict__ W_bil, const float* __restrict__ b_bil,
    const float* __restrict__ b_enc, const float* __restrict__ W_dec,
    const float* __restrict__ b_dec,
    const float* __restrict__ feat_p1, const float* __restrict__ feat_p2,
    const float* __restrict__ w_p1, const float* __restrict__ w_p2,
    const float* __restrict__ w_n,
    const int* __restrict__ src_p1, const int* __restrict__ dst_p1,
    const int* __restrict__ src_p2, const int* __restrict__ dst_p2,
    const int* __restrict__ src_n,  const int* __restrict__ dst_n)
{
    const int b = blockIdx.x;
    const int tid = threadIdx.x;

    __shared__ float sY[Knod * FOUT];
    __shared__ float sAgg[Knod * FOUT];
    __shared__ float sH[2][Knod * FOUT];
    __shared__ float sWb[FOUT][FOUT + 1];
    __shared__ float sPool[3][FOUT];
    __shared__ float sA[2][FOUT];
    __shared__ float sU[FOUT];
    __shared__ float sBenc[FOUT];
    __shared__ float sV[2][FOUT];
    __shared__ float sHd[2][FIN];
    __shared__ float sRed[128];
    __shared__ float sInv[Knod];
    __shared__ float sDegS[Knod], sDegD[Knod];
    __shared__ int sSrc[Eedg], sDst[Eedg];
    __shared__ float sWe[Eedg];
    __shared__ float sScal[12];

    // constants
    if (tid < FOUT) sBenc[tid] = b_enc[tid];
    for (int i = tid; i < FOUT * FOUT; i += 128) sWb[i >> 6][i & 63] = W_bil[i];
    __syncthreads();

    // ---------------- encoder: three samples ----------------
    for (int s = 0; s < 3; s++) {
        const float* Yb = g_Y + ((long)s * (Bsz * Knod) + (long)b * Knod) * FOUT;
        const float* wp = (s == 0) ? w_p1 : (s == 1) ? w_p2 : w_n;
        const int* sp = (s == 0) ? src_p1 : (s == 1) ? src_p2 : src_n;
        const int* dp = (s == 0) ? dst_p1 : (s == 1) ? dst_p2 : dst_n;

        if (tid < Eedg) {
            sSrc[tid] = sp[(long)b * Eedg + tid];
            sDst[tid] = dp[(long)b * Eedg + tid];
            sWe[tid]  = wp[(long)b * Eedg + tid];
        }
        for (int i = tid; i < Knod * FOUT; i += 128) {
            sY[i] = Yb[i];
            sAgg[i] = 0.f;
        }
        __syncthreads();

        // spmm aggregation (x row 0 is zero: skip src==0)
        if (tid < FOUT) {
            const int f = tid;
            for (int e = 0; e < Eedg; e++) {
                int se = sSrc[e];
                if (se != 0) sAgg[sDst[e] * FOUT + f] += sWe[e] * sY[se * FOUT + f];
            }
        }
        __syncthreads();

        // h = relu(agg + b_enc)
        for (int i = tid; i < Knod * FOUT; i += 128) {
            sAgg[i] = fmaxf(sAgg[i] + sBenc[i & 63], 0.f);
        }
        __syncthreads();

        // pool (raw h mean over k)
        if (tid < FOUT) {
            float p = 0.f;
            for (int k = 0; k < Knod; k++) p += sAgg[k * FOUT + tid];
            sPool[s][tid] = p * (1.f / Knod);
        }

        if (s < 2) {
            // per-row inverse norms
            {
                int k = tid >> 3, j = tid & 7;
                float ssq = 0.f;
                for (int f = j; f < FOUT; f += 8) {
                    float v = sAgg[k * FOUT + f];
                    ssq += v * v;
                }
                ssq += __shfl_xor_sync(0xffffffff, ssq, 1);
                ssq += __shfl_xor_sync(0xffffffff, ssq, 2);
                ssq += __shfl_xor_sync(0xffffffff, ssq, 4);
                if (j == 0) sInv[k] = 1.f / fmaxf(sqrtf(ssq), 1e-12f);
            }
            __syncthreads();
            for (int i = tid; i < Knod * FOUT; i += 128)
                sH[s][i] = sAgg[i] * sInv[i >> 6];

            // anchor = relu(Y[0] + b_enc), then l2n
            if (tid < FOUT) sA[s][tid] = fmaxf(sY[tid] + sBenc[tid], 0.f);
            __syncthreads();
            {
                float v = (tid < FOUT) ? sA[s][tid] : 0.f;
                float ssq = blockReduceSum(v * v, sRed);
                float inv = 1.f / fmaxf(sqrtf(ssq), 1e-12f);
                if (tid < FOUT) sA[s][tid] *= inv;
            }
        }
        __syncthreads();

        // pool l2n
        {
            float v = (tid < FOUT) ? sPool[s][tid] : 0.f;
            float ssq = blockReduceSum(v * v, sRed);
            float inv = 1.f / fmaxf(sqrtf(ssq), 1e-12f);
            if (tid < FOUT) sPool[s][tid] *= inv;
        }
        __syncthreads();
    }

    // ---------------- discriminators ----------------
    const float bb = b_bil[0];
    for (int t = 0; t < 2; t++) {
        if (tid < FOUT) {
            float u = 0.f;
            for (int k = 0; k < FOUT; k++) u += sWb[tid][k] * sA[t][k];
            sU[tid] = u;
        }
        __syncthreads();
        float vps = (tid < FOUT) ? sPool[t][tid] * sU[tid] : 0.f;
        float dps = blockReduceSum(vps, sRed);
        float vns = (tid < FOUT) ? sPool[2][tid] * sU[tid] : 0.f;
        float dns = blockReduceSum(vns, sRed);
        if (tid == 0) {
            sScal[t]     = 1.f / (1.f + expf(-(dps + bb)));  // ps
            sScal[2 + t] = 1.f / (1.f + expf(-(dns + bb)));  // ns
        }
        __syncthreads();
    }

    // ---------------- decoders (anchor row only) ----------------
    for (int s = 0; s < 2; s++) {
        const float* wp = (s == 0) ? w_p1 : w_p2;
        const int* sp = (s == 0) ? src_p1 : src_p2;
        const int* dp = (s == 0) ? dst_p1 : dst_p2;
        if (tid < Eedg) {
            sSrc[tid] = sp[(long)b * Eedg + tid];
            sDst[tid] = dp[(long)b * Eedg + tid];
            sWe[tid]  = wp[(long)b * Eedg + tid];
        }
        if (tid < Knod) { sDegS[tid] = 0.f; sDegD[tid] = 0.f; }
        __syncthreads();
        if (tid < Eedg) {
            atomicAdd(&sDegS[sSrc[tid]], 1.f);
            atomicAdd(&sDegD[sDst[tid]], 1.f);
        }
        __syncthreads();
        if (tid < FOUT) {
            float v = 0.f;
            for (int e = 0; e < Eedg; e++) {
                if (sDst[e] == 0) {
                    int se = sSrc[e];
                    v += sWe[e] * rsqrtf(fmaxf(sDegS[se], 1.f)) * sH[s][se * FOUT + tid];
                }
            }
            sV[s][tid] = v;
        }
        if (tid == 0) sScal[4 + s] = rsqrtf(fmaxf(sDegD[0], 1.f));
        __syncthreads();
    }

    // hd = relu((v @ W_dec) * ndst0 + b_dec) for both decoders in one W_dec sweep
    const float nd0 = sScal[4], nd1 = sScal[5];
    for (int c = 0; c < 3; c++) {
        int i = tid + c * 128;
        if (i < FIN) {
            float a0 = 0.f, a1 = 0.f;
#pragma unroll
            for (int f = 0; f < FOUT; f++) {
                float w = W_dec[f * FIN + i];
                a0 += sV[0][f] * w;
                a1 += sV[1][f] * w;
            }
            float bd = b_dec[i];
            sHd[0][i] = fmaxf(a0 * nd0 + bd, 0.f);
            sHd[1][i] = fmaxf(a1 * nd1 + bd, 0.f);
        }
    }
    __syncthreads();

    // norms of hd rows
    float l0 = 0.f, l1 = 0.f;
    for (int c = 0; c < 3; c++) {
        int i = tid + c * 128;
        if (i < FIN) { l0 += sHd[0][i] * sHd[0][i]; l1 += sHd[1][i] * sHd[1][i]; }
    }
    float n0 = blockReduceSum(l0, sRed);
    float n1 = blockReduceSum(l1, sRed);
    float inv0 = 1.f / fmaxf(sqrtf(n0), 1e-12f);
    float inv1 = 1.f / fmaxf(sqrtf(n1), 1e-12f);

    // squared error vs original anchor features
    const float* ori0 = feat_p1 + (long)b * Knod * FIN;
    const float* ori1 = feat_p2 + (long)b * Knod * FIN;
    float e0 = 0.f, e1 = 0.f;
    for (int c = 0; c < 3; c++) {
        int i = tid + c * 128;
        if (i < FIN) {
            float d0 = sHd[0][i] * inv0 - ori0[i];
            float d1 = sHd[1][i] * inv1 - ori1[i];
            e0 += d0 * d0;
            e1 += d1 * d1;
        }
    }
    float S0 = blockReduceSum(e0, sRed);
    float S1 = blockReduceSum(e1, sRed);

    if (tid == 0) {
        float ps1 = sScal[0], ps2 = sScal[1], ns1 = sScal[2], ns2 = sScal[3];
        g_ssq1[b] = S0;
        g_ssq2[b] = S1;
        g_lt1[b] = logf(ps1) + logf(1.f - ns1);
        g_lt2[b] = logf(ps2) + logf(1.f - ns2);
        g_contr[b] = (ns1 - ps1 + 1.f) * 0.5f + (ns2 - ps2 + 1.f) * 0.5f;
    }
}

// ---------------------------------------------------------------------------
// Kernel 3: global reduction -> L (out[0]) and gen scalar
// ---------------------------------------------------------------------------
__global__ void __launch_bounds__(256) finalize_kernel(float* out) {
    __shared__ float sR[256 * 4];
    int tid = threadIdx.x;
    float a = 0.f, c = 0.f, m1 = 0.f, m2 = 0.f;
    for (int i = tid; i < Bsz; i += 256) {
        a += g_ssq1[i];
        c += g_ssq2[i];
        m1 += g_lt1[i];
        m2 += g_lt2[i];
    }
    sR[tid] = a; sR[256 + tid] = c; sR[512 + tid] = m1; sR[768 + tid] = m2;
    __syncthreads();
    for (int s = 128; s > 0; s >>= 1) {
        if (tid < s) {
            sR[tid] += sR[tid + s];
            sR[256 + tid] += sR[256 + tid + s];
            sR[512 + tid] += sR[512 + tid + s];
            sR[768 + tid] += sR[768 + tid + s];
        }
        __syncthreads();
    }
    if (tid == 0) {
        float Ssq1 = sR[0], Ssq2 = sR[256], M1 = sR[512], M2 = sR[768];
        float m1m = M1 / (float)Bsz, m2m = M2 / (float)Bsz;
        float L_con = -(m1m + m2m) * 0.25f;
        float L_gen = (Ssq1 + Ssq2) / (2.f * (float)Bsz * (float)FIN);
        out[0] = ALPHA * L_con + BETA * L_gen;
        g_gen = (sqrtf(Ssq1) + sqrtf(Ssq2)) / (2.f * sqrtf((float)FIN));
    }
}

// ---------------------------------------------------------------------------
// Kernel 4: scores
// ---------------------------------------------------------------------------
__global__ void scores_kernel(float* out) {
    int i = blockIdx.x * blockDim.x + threadIdx.x;
    if (i < Bsz) out[1 + i] = ALPHA * g_contr[i] + BETA * g_gen;
}

// ---------------------------------------------------------------------------
extern "C" void kernel_launch(void* const* d_in, const int* in_sizes, int n_in,
                              void* d_out, int out_size) {
    const float* feat_p1 = (const float*)d_in[0];
    const float* feat_p2 = (const float*)d_in[1];
    const float* feat_n  = (const float*)d_in[2];
    const float* w_p1    = (const float*)d_in[3];
    const float* w_p2    = (const float*)d_in[4];
    const float* w_n     = (const float*)d_in[5];
    const float* W_enc   = (const float*)d_in[6];
    const float* b_enc   = (const float*)d_in[7];
    const float* W_dec   = (const float*)d_in[8];
    const float* b_dec   = (const float*)d_in[9];
    const float* W_bil   = (const float*)d_in[10];
    const float* b_bil   = (const float*)d_in[11];
    const int* src_p1 = (const int*)d_in[12];
    const int* dst_p1 = (const int*)d_in[13];
    const int* src_p2 = (const int*)d_in[14];
    const int* dst_p2 = (const int*)d_in[15];
    const int* src_n  = (const int*)d_in[16];
    const int* dst_n  = (const int*)d_in[17];
    float* out = (float*)d_out;

    dim3 g1((Bsz * Knod) / 64, 1, 3);
    gemm_enc<<<g1, 256>>>(feat_p1, feat_p2, feat_n, W_enc);

    graph_kernel<<<Bsz, 128>>>(W_bil, b_bil, b_enc, W_dec, b_dec,
                               feat_p1, feat_p2,
                               w_p1, w_p2, w_n,
                               src_p1, dst_p1, src_p2, dst_p2, src_n, dst_n);

    finalize_kernel<<<1, 256>>>(out);
    scores_kernel<<<(Bsz + 255) / 256, 256>>>(out);
}